// round 5
// baseline (speedup 1.0000x reference)
#include <cuda_runtime.h>
#include <cuda_bf16.h>
#include <math.h>

#define NN 100000
#define EE 1600000
#define HH 128
#define LL 2
#define GG 64
#define TILE 64
#define SCAN_B 512
#define NB ((NN + SCAN_B - 1) / SCAN_B)   // 196

// Scratch (device globals; no allocation allowed)
__device__ float g_h[NN * HH];
__device__ float g_hb[NN * HH];
__device__ float g_pooled[GG * HH];
__device__ float g_cnt[GG];
__device__ int   g_deg[NN];
__device__ int   g_row[NN + 1];
__device__ int   g_cursor[NN];
__device__ int   g_bsum[NB];
__device__ int   g_bsum2[256];
__device__ int   g_csr_src[EE];
__device__ float g_csr_attr[EE];

// ---------------------------------------------------------------------------
__global__ void init_kernel() {
    int i = blockIdx.x * blockDim.x + threadIdx.x;
    if (i < NN) g_deg[i] = 0;
    if (i < GG * HH) g_pooled[i] = 0.f;
    if (i < GG) g_cnt[i] = 0.f;
}

// ---------------------------------------------------------------------------
// Node encoder: h = x @ enc_w + enc_b (rank-1).
// ---------------------------------------------------------------------------
__global__ void encode_kernel(const float* __restrict__ x,
                              const float* __restrict__ enc_w,
                              const float* __restrict__ enc_b) {
    int idx = blockIdx.x * blockDim.x + threadIdx.x;
    if (idx >= NN * (HH / 4)) return;
    int n  = idx >> 5;
    int c4 = (idx & 31) * 4;
    float xv = x[n];
    float4 w = *(const float4*)(enc_w + c4);
    float4 b = *(const float4*)(enc_b + c4);
    float4 h;
    h.x = fmaf(xv, w.x, b.x);
    h.y = fmaf(xv, w.y, b.y);
    h.z = fmaf(xv, w.z, b.z);
    h.w = fmaf(xv, w.w, b.w);
    *(float4*)(g_h + (size_t)n * HH + c4) = h;
}

// ---------------------------------------------------------------------------
// CSR build: histogram -> scan -> scatter
// ---------------------------------------------------------------------------
__global__ void hist_kernel(const int* __restrict__ ei) {
    int e = blockIdx.x * blockDim.x + threadIdx.x;
    if (e < EE) atomicAdd(&g_deg[ei[EE + e]], 1);
}

__global__ void scan1_kernel() {
    __shared__ int sh[SCAN_B];
    int t = threadIdx.x;
    int i = blockIdx.x * SCAN_B + t;
    int v = (i < NN) ? g_deg[i] : 0;
    sh[t] = v;
    __syncthreads();
    for (int off = 1; off < SCAN_B; off <<= 1) {
        int add = (t >= off) ? sh[t - off] : 0;
        __syncthreads();
        sh[t] += add;
        __syncthreads();
    }
    if (i < NN) g_row[i] = sh[t] - v;
    if (t == SCAN_B - 1) g_bsum[blockIdx.x] = sh[t];
}

__global__ void scan2_kernel() {
    __shared__ int sh[256];
    int t = threadIdx.x;
    int v = (t < NB) ? g_bsum[t] : 0;
    sh[t] = v;
    __syncthreads();
    for (int off = 1; off < 256; off <<= 1) {
        int add = (t >= off) ? sh[t - off] : 0;
        __syncthreads();
        sh[t] += add;
        __syncthreads();
    }
    g_bsum2[t] = sh[t] - v;
}

__global__ void scan3_kernel() {
    int i = blockIdx.x * blockDim.x + threadIdx.x;
    if (i < NN) {
        int val = g_row[i] + g_bsum2[i / SCAN_B];
        g_row[i] = val;
        g_cursor[i] = val;
    }
    if (i == 0) g_row[NN] = EE;
}

__global__ void scatter_kernel(const int* __restrict__ ei,
                               const float* __restrict__ eattr) {
    int e = blockIdx.x * blockDim.x + threadIdx.x;
    if (e >= EE) return;
    int d = ei[EE + e];
    int pos = atomicAdd(&g_cursor[d], 1);
    g_csr_src[pos] = ei[e];
    g_csr_attr[pos] = eattr[e];
}

// ---------------------------------------------------------------------------
// Fused layer: per 64-node tile
//   agg phase (warp gathers its 4 rows' edges from h_old via CSR) -> z in smem
//   GEMM1 -> GEMM2 -> BN(eval)+ReLU -> h_new
// Persistent 148 blocks x 512 threads; weights in smem (128 KB) + tiles (64 KB).
// ---------------------------------------------------------------------------
__global__ void __launch_bounds__(512, 1)
layer_kernel(const float* __restrict__ h_old, float* __restrict__ h_new,
             const float* __restrict__ w1, const float* __restrict__ b1,
             const float* __restrict__ w2, const float* __restrict__ b2,
             const float* __restrict__ gamma, const float* __restrict__ beta,
             const float* __restrict__ eps,
             const float* __restrict__ ew, const float* __restrict__ eb,
             int l) {
    extern __shared__ float smem[];
    float* w1s = smem;                  // 128*128
    float* w2s = w1s + HH * HH;         // 128*128
    float* zt  = w2s + HH * HH;         // TILE*128
    float* yt  = zt + TILE * HH;        // TILE*128

    const float* w1l = w1 + (size_t)l * HH * HH;
    const float* w2l = w2 + (size_t)l * HH * HH;
    int t = threadIdx.x;

    for (int i = t; i < HH * HH / 4; i += blockDim.x) {
        ((float4*)w1s)[i] = ((const float4*)w1l)[i];
        ((float4*)w2s)[i] = ((const float4*)w2l)[i];
    }

    const float epsl = 1.0f + eps[l];
    const float inv_std = 0.9999950000374998f;  // 1/sqrt(1+1e-5)

    int rg = t >> 5;        // warp id (0..15) -> 4 rows each
    int lane = t & 31;
    int c4 = lane * 4;

    float4 wv  = *(const float4*)(ew + c4);
    float4 bv  = *(const float4*)(eb + c4);
    float4 b1v = *(const float4*)(b1 + (size_t)l * HH + c4);
    float4 b2v = *(const float4*)(b2 + (size_t)l * HH + c4);
    float4 gv  = *(const float4*)(gamma + (size_t)l * HH + c4);
    float4 bev = *(const float4*)(beta + (size_t)l * HH + c4);
    gv.x *= inv_std; gv.y *= inv_std; gv.z *= inv_std; gv.w *= inv_std;

    __syncthreads();

    const int ntiles = (NN + TILE - 1) / TILE;
    for (int tile = blockIdx.x; tile < ntiles; tile += gridDim.x) {
        int n0 = tile * TILE;
        int nrows = min(TILE, NN - n0);

        // ---- Aggregation phase: z[r] = (1+eps)*h_old[n] + sum relu(h_old[src]+ea)
        #pragma unroll
        for (int i = 0; i < 4; i++) {
            int r = rg * 4 + i;
            int n = n0 + r;
            float4 z4 = make_float4(0.f, 0.f, 0.f, 0.f);
            if (r < nrows) {
                int r0 = g_row[n];
                int r1 = g_row[n + 1];
                float4 acc = make_float4(0.f, 0.f, 0.f, 0.f);
                for (int base = r0; base < r1; base += 32) {
                    int idx = base + lane;
                    int s = 0; float a = 0.f;
                    if (idx < r1) { s = g_csr_src[idx]; a = g_csr_attr[idx]; }
                    int cnt = min(32, r1 - base);
                    int j = 0;
                    for (; j + 3 < cnt; j += 4) {
                        int   s0 = __shfl_sync(0xffffffffu, s, j + 0);
                        int   s1 = __shfl_sync(0xffffffffu, s, j + 1);
                        int   s2 = __shfl_sync(0xffffffffu, s, j + 2);
                        int   s3 = __shfl_sync(0xffffffffu, s, j + 3);
                        float a0 = __shfl_sync(0xffffffffu, a, j + 0);
                        float a1 = __shfl_sync(0xffffffffu, a, j + 1);
                        float a2 = __shfl_sync(0xffffffffu, a, j + 2);
                        float a3 = __shfl_sync(0xffffffffu, a, j + 3);
                        float4 h0 = *(const float4*)(h_old + (size_t)s0 * HH + c4);
                        float4 h1 = *(const float4*)(h_old + (size_t)s1 * HH + c4);
                        float4 h2 = *(const float4*)(h_old + (size_t)s2 * HH + c4);
                        float4 h3 = *(const float4*)(h_old + (size_t)s3 * HH + c4);
                        acc.x += fmaxf(h0.x + fmaf(a0, wv.x, bv.x), 0.f);
                        acc.y += fmaxf(h0.y + fmaf(a0, wv.y, bv.y), 0.f);
                        acc.z += fmaxf(h0.z + fmaf(a0, wv.z, bv.z), 0.f);
                        acc.w += fmaxf(h0.w + fmaf(a0, wv.w, bv.w), 0.f);
                        acc.x += fmaxf(h1.x + fmaf(a1, wv.x, bv.x), 0.f);
                        acc.y += fmaxf(h1.y + fmaf(a1, wv.y, bv.y), 0.f);
                        acc.z += fmaxf(h1.z + fmaf(a1, wv.z, bv.z), 0.f);
                        acc.w += fmaxf(h1.w + fmaf(a1, wv.w, bv.w), 0.f);
                        acc.x += fmaxf(h2.x + fmaf(a2, wv.x, bv.x), 0.f);
                        acc.y += fmaxf(h2.y + fmaf(a2, wv.y, bv.y), 0.f);
                        acc.z += fmaxf(h2.z + fmaf(a2, wv.z, bv.z), 0.f);
                        acc.w += fmaxf(h2.w + fmaf(a2, wv.w, bv.w), 0.f);
                        acc.x += fmaxf(h3.x + fmaf(a3, wv.x, bv.x), 0.f);
                        acc.y += fmaxf(h3.y + fmaf(a3, wv.y, bv.y), 0.f);
                        acc.z += fmaxf(h3.z + fmaf(a3, wv.z, bv.z), 0.f);
                        acc.w += fmaxf(h3.w + fmaf(a3, wv.w, bv.w), 0.f);
                    }
                    for (; j < cnt; j++) {
                        int   sj = __shfl_sync(0xffffffffu, s, j);
                        float aj = __shfl_sync(0xffffffffu, a, j);
                        float4 hv = *(const float4*)(h_old + (size_t)sj * HH + c4);
                        acc.x += fmaxf(hv.x + fmaf(aj, wv.x, bv.x), 0.f);
                        acc.y += fmaxf(hv.y + fmaf(aj, wv.y, bv.y), 0.f);
                        acc.z += fmaxf(hv.z + fmaf(aj, wv.z, bv.z), 0.f);
                        acc.w += fmaxf(hv.w + fmaf(aj, wv.w, bv.w), 0.f);
                    }
                }
                float4 hv = *(const float4*)(h_old + (size_t)n * HH + c4);
                z4.x = fmaf(epsl, hv.x, acc.x);
                z4.y = fmaf(epsl, hv.y, acc.y);
                z4.z = fmaf(epsl, hv.z, acc.z);
                z4.w = fmaf(epsl, hv.w, acc.w);
            }
            *(float4*)(zt + (rg * 4 + i) * HH + c4) = z4;
        }
        __syncthreads();

        // ---- GEMM1: y = relu(z @ w1 + b1)
        float4 acc0 = b1v, acc1 = b1v, acc2 = b1v, acc3 = b1v;
        #pragma unroll 4
        for (int k = 0; k < HH; k++) {
            float4 w = *(const float4*)(w1s + k * HH + c4);
            float z0 = zt[(rg * 4 + 0) * HH + k];
            float z1 = zt[(rg * 4 + 1) * HH + k];
            float z2 = zt[(rg * 4 + 2) * HH + k];
            float z3 = zt[(rg * 4 + 3) * HH + k];
            acc0.x = fmaf(z0, w.x, acc0.x); acc0.y = fmaf(z0, w.y, acc0.y);
            acc0.z = fmaf(z0, w.z, acc0.z); acc0.w = fmaf(z0, w.w, acc0.w);
            acc1.x = fmaf(z1, w.x, acc1.x); acc1.y = fmaf(z1, w.y, acc1.y);
            acc1.z = fmaf(z1, w.z, acc1.z); acc1.w = fmaf(z1, w.w, acc1.w);
            acc2.x = fmaf(z2, w.x, acc2.x); acc2.y = fmaf(z2, w.y, acc2.y);
            acc2.z = fmaf(z2, w.z, acc2.z); acc2.w = fmaf(z2, w.w, acc2.w);
            acc3.x = fmaf(z3, w.x, acc3.x); acc3.y = fmaf(z3, w.y, acc3.y);
            acc3.z = fmaf(z3, w.z, acc3.z); acc3.w = fmaf(z3, w.w, acc3.w);
        }
        *(float4*)(yt + (rg * 4 + 0) * HH + c4) =
            make_float4(fmaxf(acc0.x,0.f), fmaxf(acc0.y,0.f), fmaxf(acc0.z,0.f), fmaxf(acc0.w,0.f));
        *(float4*)(yt + (rg * 4 + 1) * HH + c4) =
            make_float4(fmaxf(acc1.x,0.f), fmaxf(acc1.y,0.f), fmaxf(acc1.z,0.f), fmaxf(acc1.w,0.f));
        *(float4*)(yt + (rg * 4 + 2) * HH + c4) =
            make_float4(fmaxf(acc2.x,0.f), fmaxf(acc2.y,0.f), fmaxf(acc2.z,0.f), fmaxf(acc2.w,0.f));
        *(float4*)(yt + (rg * 4 + 3) * HH + c4) =
            make_float4(fmaxf(acc3.x,0.f), fmaxf(acc3.y,0.f), fmaxf(acc3.z,0.f), fmaxf(acc3.w,0.f));
        __syncthreads();

        // ---- GEMM2: h2 = y @ w2 + b2
        acc0 = b2v; acc1 = b2v; acc2 = b2v; acc3 = b2v;
        #pragma unroll 4
        for (int k = 0; k < HH; k++) {
            float4 w = *(const float4*)(w2s + k * HH + c4);
            float z0 = yt[(rg * 4 + 0) * HH + k];
            float z1 = yt[(rg * 4 + 1) * HH + k];
            float z2 = yt[(rg * 4 + 2) * HH + k];
            float z3 = yt[(rg * 4 + 3) * HH + k];
            acc0.x = fmaf(z0, w.x, acc0.x); acc0.y = fmaf(z0, w.y, acc0.y);
            acc0.z = fmaf(z0, w.z, acc0.z); acc0.w = fmaf(z0, w.w, acc0.w);
            acc1.x = fmaf(z1, w.x, acc1.x); acc1.y = fmaf(z1, w.y, acc1.y);
            acc1.z = fmaf(z1, w.z, acc1.z); acc1.w = fmaf(z1, w.w, acc1.w);
            acc2.x = fmaf(z2, w.x, acc2.x); acc2.y = fmaf(z2, w.y, acc2.y);
            acc2.z = fmaf(z2, w.z, acc2.z); acc2.w = fmaf(z2, w.w, acc2.w);
            acc3.x = fmaf(z3, w.x, acc3.x); acc3.y = fmaf(z3, w.y, acc3.y);
            acc3.z = fmaf(z3, w.z, acc3.z); acc3.w = fmaf(z3, w.w, acc3.w);
        }

        // ---- BN(eval) + ReLU, store h_new
        #pragma unroll
        for (int i = 0; i < 4; i++) {
            int r = rg * 4 + i;
            if (r < nrows) {
                float4 a = (i == 0) ? acc0 : (i == 1) ? acc1 : (i == 2) ? acc2 : acc3;
                float4 o;
                o.x = fmaxf(fmaf(gv.x, a.x, bev.x), 0.f);
                o.y = fmaxf(fmaf(gv.y, a.y, bev.y), 0.f);
                o.z = fmaxf(fmaf(gv.z, a.z, bev.z), 0.f);
                o.w = fmaxf(fmaf(gv.w, a.w, bev.w), 0.f);
                *(float4*)(h_new + (size_t)(n0 + r) * HH + c4) = o;
            }
        }
        __syncthreads();
    }
}

// ---------------------------------------------------------------------------
// Mean-pool by graph (batch sorted -> run-length + few atomics).
// ---------------------------------------------------------------------------
__global__ void pool_kernel(const int* __restrict__ batch) {
    int n0 = blockIdx.x * 256;
    int c = threadIdx.x;
    int nend = min(n0 + 256, NN);
    int gprev = batch[n0];
    float acc = 0.f;
    float cacc = 0.f;
    for (int n = n0; n < nend; n++) {
        int g = batch[n];
        if (g != gprev) {
            atomicAdd(&g_pooled[gprev * HH + c], acc);
            if (c == 0) atomicAdd(&g_cnt[gprev], cacc);
            acc = 0.f; cacc = 0.f; gprev = g;
        }
        acc += g_h[(size_t)n * HH + c];
        cacc += 1.f;
    }
    atomicAdd(&g_pooled[gprev * HH + c], acc);
    if (c == 0) atomicAdd(&g_cnt[gprev], cacc);
}

// ---------------------------------------------------------------------------
// Classifier: out = sigmoid(relu(pooled @ cw1 + cb1) @ cw2 + cb2)
// ---------------------------------------------------------------------------
__global__ void cls_kernel(const float* __restrict__ cw1, const float* __restrict__ cb1,
                           const float* __restrict__ cw2, const float* __restrict__ cb2,
                           float* __restrict__ out) {
    __shared__ float p[HH];
    __shared__ float hcs[64];
    int g = blockIdx.x;
    int t = threadIdx.x;
    float inv = 1.f / fmaxf(g_cnt[g], 1.f);
    p[t] = g_pooled[g * HH + t] * inv;
    __syncthreads();
    if (t < 64) {
        float s = cb1[t];
        #pragma unroll 8
        for (int k = 0; k < HH; k++) s = fmaf(p[k], cw1[k * 64 + t], s);
        hcs[t] = fmaxf(s, 0.f);
    }
    __syncthreads();
    if (t < 32) {
        float s = hcs[t] * cw2[t] + hcs[t + 32] * cw2[t + 32];
        #pragma unroll
        for (int off = 16; off; off >>= 1) s += __shfl_down_sync(0xffffffffu, s, off);
        if (t == 0) out[g] = 1.f / (1.f + expf(-(s + cb2[0])));
    }
}

// ---------------------------------------------------------------------------
extern "C" void kernel_launch(void* const* d_in, const int* in_sizes, int n_in,
                              void* d_out, int out_size) {
    const float* x      = (const float*)d_in[0];
    const int*   ei     = (const int*)d_in[1];
    const float* eattr  = (const float*)d_in[2];
    const int*   batch  = (const int*)d_in[3];
    const float* enc_w  = (const float*)d_in[4];
    const float* enc_b  = (const float*)d_in[5];
    const float* eenc_w = (const float*)d_in[6];
    const float* eenc_b = (const float*)d_in[7];
    const float* eps    = (const float*)d_in[8];
    const float* w1     = (const float*)d_in[9];
    const float* b1     = (const float*)d_in[10];
    const float* w2     = (const float*)d_in[11];
    const float* b2     = (const float*)d_in[12];
    const float* gamma  = (const float*)d_in[13];
    const float* beta   = (const float*)d_in[14];
    const float* cw1    = (const float*)d_in[15];
    const float* cb1    = (const float*)d_in[16];
    const float* cw2    = (const float*)d_in[17];
    const float* cb2    = (const float*)d_in[18];
    float* out = (float*)d_out;

    const int smem_bytes = (2 * HH * HH + 2 * TILE * HH) * (int)sizeof(float);  // 192 KB
    cudaFuncSetAttribute(layer_kernel, cudaFuncAttributeMaxDynamicSharedMemorySize, smem_bytes);

    init_kernel<<<(NN + 255) / 256, 256>>>();
    encode_kernel<<<(NN * (HH / 4) + 255) / 256, 256>>>(x, enc_w, enc_b);

    // CSR build (edges are layer-invariant)
    hist_kernel<<<(EE + 255) / 256, 256>>>(ei);
    scan1_kernel<<<NB, SCAN_B>>>();
    scan2_kernel<<<1, 256>>>();
    scan3_kernel<<<(NN + 255) / 256, 256>>>();
    scatter_kernel<<<(EE + 255) / 256, 256>>>(ei, eattr);

    // Fused layers with double-buffered h: g_h -> g_hb -> g_h
    float* hA = nullptr; float* hB = nullptr;
    cudaGetSymbolAddress((void**)&hA, g_h);
    cudaGetSymbolAddress((void**)&hB, g_hb);
    layer_kernel<<<148, 512, smem_bytes>>>(hA, hB, w1, b1, w2, b2, gamma, beta, eps, eenc_w, eenc_b, 0);
    layer_kernel<<<148, 512, smem_bytes>>>(hB, hA, w1, b1, w2, b2, gamma, beta, eps, eenc_w, eenc_b, 1);

    pool_kernel<<<(NN + 255) / 256, 128>>>(batch);
    cls_kernel<<<GG, 128>>>(cw1, cb1, cw2, cb2, out);
}

// round 6
// speedup vs baseline: 1.1879x; 1.1879x over previous
#include <cuda_runtime.h>
#include <cuda_bf16.h>
#include <math.h>
#include <stdint.h>

#define NN 100000
#define EE 1600000
#define HH 128
#define LL 2
#define GG 64
#define TILE 64
#define ZS 132        // activation smem row stride (floats): conflict-free A-frags
#define WS 136        // weight smem row stride (floats): conflict-free B-frags
#define SCAN_B 512
#define NB ((NN + SCAN_B - 1) / SCAN_B)   // 196

// Scratch (device globals; no allocation allowed)
__device__ float g_h[NN * HH];
__device__ float g_agg[NN * HH];
__device__ float g_pooled[GG * HH];
__device__ float g_cnt[GG];
__device__ int   g_deg[NN];
__device__ int   g_row[NN + 1];
__device__ int   g_cursor[NN];
__device__ int   g_bsum[NB];
__device__ int   g_bsum2[256];
__device__ int   g_csr_src[EE];
__device__ float g_csr_attr[EE];

// ---------------------------------------------------------------------------
__global__ void init_kernel() {
    int i = blockIdx.x * blockDim.x + threadIdx.x;
    if (i < NN) g_deg[i] = 0;
    if (i < GG * HH) g_pooled[i] = 0.f;
    if (i < GG) g_cnt[i] = 0.f;
}

// ---------------------------------------------------------------------------
// Node encoder: h = x @ enc_w + enc_b (rank-1).
// ---------------------------------------------------------------------------
__global__ void encode_kernel(const float* __restrict__ x,
                              const float* __restrict__ enc_w,
                              const float* __restrict__ enc_b) {
    int idx = blockIdx.x * blockDim.x + threadIdx.x;
    if (idx >= NN * (HH / 4)) return;
    int n  = idx >> 5;
    int c4 = (idx & 31) * 4;
    float xv = x[n];
    float4 w = *(const float4*)(enc_w + c4);
    float4 b = *(const float4*)(enc_b + c4);
    float4 h;
    h.x = fmaf(xv, w.x, b.x);
    h.y = fmaf(xv, w.y, b.y);
    h.z = fmaf(xv, w.z, b.z);
    h.w = fmaf(xv, w.w, b.w);
    *(float4*)(g_h + (size_t)n * HH + c4) = h;
}

// ---------------------------------------------------------------------------
// CSR build: histogram -> scan -> scatter
// ---------------------------------------------------------------------------
__global__ void hist_kernel(const int* __restrict__ ei) {
    int e = blockIdx.x * blockDim.x + threadIdx.x;
    if (e < EE) atomicAdd(&g_deg[ei[EE + e]], 1);
}

__global__ void scan1_kernel() {
    __shared__ int sh[SCAN_B];
    int t = threadIdx.x;
    int i = blockIdx.x * SCAN_B + t;
    int v = (i < NN) ? g_deg[i] : 0;
    sh[t] = v;
    __syncthreads();
    for (int off = 1; off < SCAN_B; off <<= 1) {
        int add = (t >= off) ? sh[t - off] : 0;
        __syncthreads();
        sh[t] += add;
        __syncthreads();
    }
    if (i < NN) g_row[i] = sh[t] - v;
    if (t == SCAN_B - 1) g_bsum[blockIdx.x] = sh[t];
}

__global__ void scan2_kernel() {
    __shared__ int sh[256];
    int t = threadIdx.x;
    int v = (t < NB) ? g_bsum[t] : 0;
    sh[t] = v;
    __syncthreads();
    for (int off = 1; off < 256; off <<= 1) {
        int add = (t >= off) ? sh[t - off] : 0;
        __syncthreads();
        sh[t] += add;
        __syncthreads();
    }
    g_bsum2[t] = sh[t] - v;
}

__global__ void scan3_kernel() {
    int i = blockIdx.x * blockDim.x + threadIdx.x;
    if (i < NN) {
        int val = g_row[i] + g_bsum2[i / SCAN_B];
        g_row[i] = val;
        g_cursor[i] = val;
    }
    if (i == 0) g_row[NN] = EE;
}

__global__ void scatter_kernel(const int* __restrict__ ei,
                               const float* __restrict__ eattr) {
    int e = blockIdx.x * blockDim.x + threadIdx.x;
    if (e >= EE) return;
    int d = ei[EE + e];
    int pos = atomicAdd(&g_cursor[d], 1);
    g_csr_src[pos] = ei[e];
    g_csr_attr[pos] = eattr[e];
}

// ---------------------------------------------------------------------------
// Aggregation (gather, no atomics): one warp per node. High occupancy.
// ---------------------------------------------------------------------------
__global__ void agg_kernel(const float* __restrict__ ew,
                           const float* __restrict__ eb) {
    int w = blockIdx.x * 8 + (threadIdx.x >> 5);
    if (w >= NN) return;
    int lane = threadIdx.x & 31;
    int c4 = lane * 4;
    float4 wv = *(const float4*)(ew + c4);
    float4 bv = *(const float4*)(eb + c4);
    int r0 = g_row[w];
    int r1 = g_row[w + 1];
    float4 acc = make_float4(0.f, 0.f, 0.f, 0.f);

    for (int base = r0; base < r1; base += 32) {
        int idx = base + lane;
        int s = 0; float a = 0.f;
        if (idx < r1) { s = g_csr_src[idx]; a = g_csr_attr[idx]; }
        int cnt = min(32, r1 - base);
        int j = 0;
        for (; j + 3 < cnt; j += 4) {
            int   s0 = __shfl_sync(0xffffffffu, s, j + 0);
            int   s1 = __shfl_sync(0xffffffffu, s, j + 1);
            int   s2 = __shfl_sync(0xffffffffu, s, j + 2);
            int   s3 = __shfl_sync(0xffffffffu, s, j + 3);
            float a0 = __shfl_sync(0xffffffffu, a, j + 0);
            float a1 = __shfl_sync(0xffffffffu, a, j + 1);
            float a2 = __shfl_sync(0xffffffffu, a, j + 2);
            float a3 = __shfl_sync(0xffffffffu, a, j + 3);
            float4 h0 = *(const float4*)(g_h + (size_t)s0 * HH + c4);
            float4 h1 = *(const float4*)(g_h + (size_t)s1 * HH + c4);
            float4 h2 = *(const float4*)(g_h + (size_t)s2 * HH + c4);
            float4 h3 = *(const float4*)(g_h + (size_t)s3 * HH + c4);
            acc.x += fmaxf(h0.x + fmaf(a0, wv.x, bv.x), 0.f);
            acc.y += fmaxf(h0.y + fmaf(a0, wv.y, bv.y), 0.f);
            acc.z += fmaxf(h0.z + fmaf(a0, wv.z, bv.z), 0.f);
            acc.w += fmaxf(h0.w + fmaf(a0, wv.w, bv.w), 0.f);
            acc.x += fmaxf(h1.x + fmaf(a1, wv.x, bv.x), 0.f);
            acc.y += fmaxf(h1.y + fmaf(a1, wv.y, bv.y), 0.f);
            acc.z += fmaxf(h1.z + fmaf(a1, wv.z, bv.z), 0.f);
            acc.w += fmaxf(h1.w + fmaf(a1, wv.w, bv.w), 0.f);
            acc.x += fmaxf(h2.x + fmaf(a2, wv.x, bv.x), 0.f);
            acc.y += fmaxf(h2.y + fmaf(a2, wv.y, bv.y), 0.f);
            acc.z += fmaxf(h2.z + fmaf(a2, wv.z, bv.z), 0.f);
            acc.w += fmaxf(h2.w + fmaf(a2, wv.w, bv.w), 0.f);
            acc.x += fmaxf(h3.x + fmaf(a3, wv.x, bv.x), 0.f);
            acc.y += fmaxf(h3.y + fmaf(a3, wv.y, bv.y), 0.f);
            acc.z += fmaxf(h3.z + fmaf(a3, wv.z, bv.z), 0.f);
            acc.w += fmaxf(h3.w + fmaf(a3, wv.w, bv.w), 0.f);
        }
        for (; j < cnt; j++) {
            int   sj = __shfl_sync(0xffffffffu, s, j);
            float aj = __shfl_sync(0xffffffffu, a, j);
            float4 hv = *(const float4*)(g_h + (size_t)sj * HH + c4);
            acc.x += fmaxf(hv.x + fmaf(aj, wv.x, bv.x), 0.f);
            acc.y += fmaxf(hv.y + fmaf(aj, wv.y, bv.y), 0.f);
            acc.z += fmaxf(hv.z + fmaf(aj, wv.z, bv.z), 0.f);
            acc.w += fmaxf(hv.w + fmaf(aj, wv.w, bv.w), 0.f);
        }
    }
    *(float4*)(g_agg + (size_t)w * HH + c4) = acc;
}

// ---------------------------------------------------------------------------
// TF32 helpers (3xTF32 split GEMM)
// ---------------------------------------------------------------------------
__device__ __forceinline__ uint32_t f2tf32(float f) {
    uint32_t r;
    asm("cvt.rna.tf32.f32 %0, %1;" : "=r"(r) : "f"(f));
    return r;
}
__device__ __forceinline__ void split_tf32(float f, uint32_t& h, uint32_t& l) {
    h = f2tf32(f);
    l = f2tf32(f - __uint_as_float(h));
}
__device__ __forceinline__ void mma_tf32(float* c,
                                         uint32_t a0, uint32_t a1, uint32_t a2, uint32_t a3,
                                         uint32_t b0, uint32_t b1) {
    asm volatile("mma.sync.aligned.m16n8k8.row.col.f32.tf32.tf32.f32 "
                 "{%0,%1,%2,%3}, {%4,%5,%6,%7}, {%8,%9}, {%0,%1,%2,%3};"
                 : "+f"(c[0]), "+f"(c[1]), "+f"(c[2]), "+f"(c[3])
                 : "r"(a0), "r"(a1), "r"(a2), "r"(a3), "r"(b0), "r"(b1));
}

// ---------------------------------------------------------------------------
// Fused node update via tensor cores (3xTF32):
//   z = (1+eps)*h + agg;  y = relu(z@w1+b1);  h2 = y@w2+b2;
//   h = relu(gamma*h2*inv_std + beta)   (in-place on g_h)
// Persistent 148 x 512. Warp (wm,wn) owns 16x32 output tile.
// smem: w1s/w2s padded WS=136 (conflict-free B-frags),
//       zt padded ZS=132 (conflict-free A-frags); zt reused for y.
// ---------------------------------------------------------------------------
__global__ void __launch_bounds__(512, 1)
update_kernel(const float* __restrict__ w1, const float* __restrict__ b1,
              const float* __restrict__ w2, const float* __restrict__ b2,
              const float* __restrict__ gamma, const float* __restrict__ beta,
              const float* __restrict__ eps, int l) {
    extern __shared__ float smem[];
    float* w1s = smem;                 // 128 x WS
    float* w2s = w1s + HH * WS;        // 128 x WS
    float* zt  = w2s + HH * WS;        // TILE x ZS (also holds y)

    const float* w1l = w1 + (size_t)l * HH * HH;
    const float* w2l = w2 + (size_t)l * HH * HH;
    int t = threadIdx.x;

    for (int i = t; i < HH * (HH / 4); i += 512) {
        int row = i >> 5, c4 = (i & 31) * 4;
        *(float4*)(w1s + row * WS + c4) = *(const float4*)(w1l + row * HH + c4);
        *(float4*)(w2s + row * WS + c4) = *(const float4*)(w2l + row * HH + c4);
    }

    const float epsl = 1.0f + eps[l];
    const float inv_std = 0.9999950000374998f;  // 1/sqrt(1+1e-5)

    int wid = t >> 5, lane = t & 31;
    int wm = wid >> 2;            // 0..3 -> rows [wm*16, wm*16+16)
    int wn = wid & 3;             // 0..3 -> cols [wn*32, wn*32+32)
    int gq = lane >> 2;           // groupID 0..7
    int tig = lane & 3;           // thread-in-group 0..3

    // Per-warp epilogue constants (col pairs per n8-subtile)
    float b1c[4][2], b2c[4][2], gvc[4][2], bec[4][2];
    #pragma unroll
    for (int sub = 0; sub < 4; sub++) {
        int col = wn * 32 + sub * 8 + tig * 2;
        b1c[sub][0] = b1[(size_t)l * HH + col];
        b1c[sub][1] = b1[(size_t)l * HH + col + 1];
        b2c[sub][0] = b2[(size_t)l * HH + col];
        b2c[sub][1] = b2[(size_t)l * HH + col + 1];
        gvc[sub][0] = gamma[(size_t)l * HH + col] * inv_std;
        gvc[sub][1] = gamma[(size_t)l * HH + col + 1] * inv_std;
        bec[sub][0] = beta[(size_t)l * HH + col];
        bec[sub][1] = beta[(size_t)l * HH + col + 1];
    }
    __syncthreads();

    const int ntiles = (NN + TILE - 1) / TILE;
    for (int tile = blockIdx.x; tile < ntiles; tile += gridDim.x) {
        int n0 = tile * TILE;
        int nrows = min(TILE, NN - n0);

        // ---- z-build: z = (1+eps)*h + agg  (zero OOB rows)
        #pragma unroll
        for (int i = 0; i < TILE * (HH / 4) / 512; i++) {   // 4 iters
            int idx = t + i * 512;
            int r = idx >> 5;
            int c = (idx & 31) * 4;
            float4 z4 = make_float4(0.f, 0.f, 0.f, 0.f);
            if (r < nrows) {
                size_t off = (size_t)(n0 + r) * HH + c;
                float4 hv = *(const float4*)(g_h + off);
                float4 av = *(const float4*)(g_agg + off);
                z4.x = fmaf(epsl, hv.x, av.x);
                z4.y = fmaf(epsl, hv.y, av.y);
                z4.z = fmaf(epsl, hv.z, av.z);
                z4.w = fmaf(epsl, hv.w, av.w);
            }
            *(float4*)(zt + r * ZS + c) = z4;
        }
        __syncthreads();

        // ---- GEMM1: y = relu(z @ w1 + b1)
        float c1[4][4];
        #pragma unroll
        for (int sub = 0; sub < 4; sub++) {
            c1[sub][0] = b1c[sub][0]; c1[sub][1] = b1c[sub][1];
            c1[sub][2] = b1c[sub][0]; c1[sub][3] = b1c[sub][1];
        }
        #pragma unroll
        for (int kk = 0; kk < 16; kk++) {
            int k0 = kk * 8;
            float a0f = zt[(wm * 16 + gq)     * ZS + k0 + tig];
            float a1f = zt[(wm * 16 + gq + 8) * ZS + k0 + tig];
            float a2f = zt[(wm * 16 + gq)     * ZS + k0 + tig + 4];
            float a3f = zt[(wm * 16 + gq + 8) * ZS + k0 + tig + 4];
            uint32_t a0h,a0l,a1h,a1l,a2h,a2l,a3h,a3l;
            split_tf32(a0f, a0h, a0l); split_tf32(a1f, a1h, a1l);
            split_tf32(a2f, a2h, a2l); split_tf32(a3f, a3h, a3l);
            #pragma unroll
            for (int sub = 0; sub < 4; sub++) {
                int ncol = wn * 32 + sub * 8 + gq;
                float b0f = w1s[(k0 + tig)     * WS + ncol];
                float b1f = w1s[(k0 + tig + 4) * WS + ncol];
                uint32_t b0h,b0l,b1h,b1l;
                split_tf32(b0f, b0h, b0l); split_tf32(b1f, b1h, b1l);
                mma_tf32(c1[sub], a0h,a1h,a2h,a3h, b0h,b1h);
                mma_tf32(c1[sub], a0h,a1h,a2h,a3h, b0l,b1l);
                mma_tf32(c1[sub], a0l,a1l,a2l,a3l, b0h,b1h);
            }
        }
        __syncthreads();   // all reads of zt done

        // write y = relu(c1) back into zt
        #pragma unroll
        for (int sub = 0; sub < 4; sub++) {
            int col = wn * 32 + sub * 8 + tig * 2;
            *(float2*)(zt + (wm * 16 + gq) * ZS + col) =
                make_float2(fmaxf(c1[sub][0], 0.f), fmaxf(c1[sub][1], 0.f));
            *(float2*)(zt + (wm * 16 + gq + 8) * ZS + col) =
                make_float2(fmaxf(c1[sub][2], 0.f), fmaxf(c1[sub][3], 0.f));
        }
        __syncthreads();

        // ---- GEMM2: h2 = y @ w2 + b2
        float c2r[4][4];
        #pragma unroll
        for (int sub = 0; sub < 4; sub++) {
            c2r[sub][0] = b2c[sub][0]; c2r[sub][1] = b2c[sub][1];
            c2r[sub][2] = b2c[sub][0]; c2r[sub][3] = b2c[sub][1];
        }
        #pragma unroll
        for (int kk = 0; kk < 16; kk++) {
            int k0 = kk * 8;
            float a0f = zt[(wm * 16 + gq)     * ZS + k0 + tig];
            float a1f = zt[(wm * 16 + gq + 8) * ZS + k0 + tig];
            float a2f = zt[(wm * 16 + gq)     * ZS + k0 + tig + 4];
            float a3f = zt[(wm * 16 + gq + 8) * ZS + k0 + tig + 4];
            uint32_t a0h,a0l,a1h,a1l,a2h,a2l,a3h,a3l;
            split_tf32(a0f, a0h, a0l); split_tf32(a1f, a1h, a1l);
            split_tf32(a2f, a2h, a2l); split_tf32(a3f, a3h, a3l);
            #pragma unroll
            for (int sub = 0; sub < 4; sub++) {
                int ncol = wn * 32 + sub * 8 + gq;
                float b0f = w2s[(k0 + tig)     * WS + ncol];
                float b1f = w2s[(k0 + tig + 4) * WS + ncol];
                uint32_t b0h,b0l,b1h,b1l;
                split_tf32(b0f, b0h, b0l); split_tf32(b1f, b1h, b1l);
                mma_tf32(c2r[sub], a0h,a1h,a2h,a3h, b0h,b1h);
                mma_tf32(c2r[sub], a0h,a1h,a2h,a3h, b0l,b1l);
                mma_tf32(c2r[sub], a0l,a1l,a2l,a3l, b0h,b1h);
            }
        }

        // ---- BN(eval) + ReLU, store h (in place)
        int r0 = wm * 16 + gq;
        int r1 = wm * 16 + gq + 8;
        #pragma unroll
        for (int sub = 0; sub < 4; sub++) {
            int col = wn * 32 + sub * 8 + tig * 2;
            if (r0 < nrows) {
                float2 o;
                o.x = fmaxf(fmaf(gvc[sub][0], c2r[sub][0], bec[sub][0]), 0.f);
                o.y = fmaxf(fmaf(gvc[sub][1], c2r[sub][1], bec[sub][1]), 0.f);
                *(float2*)(g_h + (size_t)(n0 + r0) * HH + col) = o;
            }
            if (r1 < nrows) {
                float2 o;
                o.x = fmaxf(fmaf(gvc[sub][0], c2r[sub][2], bec[sub][0]), 0.f);
                o.y = fmaxf(fmaf(gvc[sub][1], c2r[sub][3], bec[sub][1]), 0.f);
                *(float2*)(g_h + (size_t)(n0 + r1) * HH + col) = o;
            }
        }
        __syncthreads();
    }
}

// ---------------------------------------------------------------------------
// Mean-pool by graph (batch sorted -> run-length + few atomics).
// ---------------------------------------------------------------------------
__global__ void pool_kernel(const int* __restrict__ batch) {
    int n0 = blockIdx.x * 256;
    int c = threadIdx.x;
    int nend = min(n0 + 256, NN);
    int gprev = batch[n0];
    float acc = 0.f;
    float cacc = 0.f;
    for (int n = n0; n < nend; n++) {
        int g = batch[n];
        if (g != gprev) {
            atomicAdd(&g_pooled[gprev * HH + c], acc);
            if (c == 0) atomicAdd(&g_cnt[gprev], cacc);
            acc = 0.f; cacc = 0.f; gprev = g;
        }
        acc += g_h[(size_t)n * HH + c];
        cacc += 1.f;
    }
    atomicAdd(&g_pooled[gprev * HH + c], acc);
    if (c == 0) atomicAdd(&g_cnt[gprev], cacc);
}

// ---------------------------------------------------------------------------
// Classifier: out = sigmoid(relu(pooled @ cw1 + cb1) @ cw2 + cb2)
// ---------------------------------------------------------------------------
__global__ void cls_kernel(const float* __restrict__ cw1, const float* __restrict__ cb1,
                           const float* __restrict__ cw2, const float* __restrict__ cb2,
                           float* __restrict__ out) {
    __shared__ float p[HH];
    __shared__ float hcs[64];
    int g = blockIdx.x;
    int t = threadIdx.x;
    float inv = 1.f / fmaxf(g_cnt[g], 1.f);
    p[t] = g_pooled[g * HH + t] * inv;
    __syncthreads();
    if (t < 64) {
        float s = cb1[t];
        #pragma unroll 8
        for (int k = 0; k < HH; k++) s = fmaf(p[k], cw1[k * 64 + t], s);
        hcs[t] = fmaxf(s, 0.f);
    }
    __syncthreads();
    if (t < 32) {
        float s = hcs[t] * cw2[t] + hcs[t + 32] * cw2[t + 32];
        #pragma unroll
        for (int off = 16; off; off >>= 1) s += __shfl_down_sync(0xffffffffu, s, off);
        if (t == 0) out[g] = 1.f / (1.f + expf(-(s + cb2[0])));
    }
}

// ---------------------------------------------------------------------------
extern "C" void kernel_launch(void* const* d_in, const int* in_sizes, int n_in,
                              void* d_out, int out_size) {
    const float* x      = (const float*)d_in[0];
    const int*   ei     = (const int*)d_in[1];
    const float* eattr  = (const float*)d_in[2];
    const int*   batch  = (const int*)d_in[3];
    const float* enc_w  = (const float*)d_in[4];
    const float* enc_b  = (const float*)d_in[5];
    const float* eenc_w = (const float*)d_in[6];
    const float* eenc_b = (const float*)d_in[7];
    const float* eps    = (const float*)d_in[8];
    const float* w1     = (const float*)d_in[9];
    const float* b1     = (const float*)d_in[10];
    const float* w2     = (const float*)d_in[11];
    const float* b2     = (const float*)d_in[12];
    const float* gamma  = (const float*)d_in[13];
    const float* beta   = (const float*)d_in[14];
    const float* cw1    = (const float*)d_in[15];
    const float* cb1    = (const float*)d_in[16];
    const float* cw2    = (const float*)d_in[17];
    const float* cb2    = (const float*)d_in[18];
    float* out = (float*)d_out;

    const int smem_bytes = (2 * HH * WS + TILE * ZS) * (int)sizeof(float);  // 169 KB
    cudaFuncSetAttribute(update_kernel, cudaFuncAttributeMaxDynamicSharedMemorySize, smem_bytes);

    init_kernel<<<(NN + 255) / 256, 256>>>();
    encode_kernel<<<(NN * (HH / 4) + 255) / 256, 256>>>(x, enc_w, enc_b);

    // CSR build (edges are layer-invariant)
    hist_kernel<<<(EE + 255) / 256, 256>>>(ei);
    scan1_kernel<<<NB, SCAN_B>>>();
    scan2_kernel<<<1, 256>>>();
    scan3_kernel<<<(NN + 255) / 256, 256>>>();
    scatter_kernel<<<(EE + 255) / 256, 256>>>(ei, eattr);

    for (int l = 0; l < LL; l++) {
        agg_kernel<<<(NN + 7) / 8, 256>>>(eenc_w, eenc_b);
        update_kernel<<<148, 512, smem_bytes>>>(w1, b1, w2, b2, gamma, beta, eps, l);
    }

    pool_kernel<<<(NN + 255) / 256, 128>>>(batch);
    cls_kernel<<<GG, 128>>>(cw1, cb1, cw2, cb2, out);
}